// round 9
// baseline (speedup 1.0000x reference)
#include <cuda_runtime.h>
#include <math.h>

// Shapes (fixed):
//   x  : [B=8, C=128, D=4, H=128, W=128] -> 67,108,864 fp32 (256 MB)
//   w1, w2 : [C, C] row-major (w[o,c] = w[o*128 + c]); b1, b2 : [C]
// out = x * sigmoid(W2 @ relu(W1 @ max_{dhw}(x) + b1) + b2), gate per (b,c).

#define BC 1024              // B*C slices
#define SLICE4 16384         // 65536 floats / 4 per (b,c)

__device__ float d_gp[BC];         // per-(b,c) global max
__device__ float d_gate[BC];       // per-(b,c) sigmoid gate
__device__ unsigned d_count[8];    // per-batch tickets (zero-init; winner resets)

// ------- Kernel 1: per-slice max reduce + per-batch fused MLP -------
// One block per (b,c). After the reduce, thread 0 (ONLY) does a gpu-scope
// release fence + ticket atomic on its batch's counter. The 128th block of
// each batch computes that batch's 128 gates. Consumer d_gp reads are cold
// in L1 (per-launch L1 flush + never touched), so L2 visibility suffices.
__global__ __launch_bounds__(256) void reduce_mlp_kernel(const float4* __restrict__ x4,
                                                         const float* __restrict__ w1,
                                                         const float* __restrict__ b1,
                                                         const float* __restrict__ w2,
                                                         const float* __restrict__ b2) {
    const int bc = blockIdx.x;
    const int b = bc >> 7;
    const float4* base = x4 + (size_t)bc * SLICE4;
    const int t = threadIdx.x;

    float m0 = -INFINITY, m1 = -INFINITY, m2 = -INFINITY, m3 = -INFINITY;
    #pragma unroll
    for (int i = 0; i < 16; i++) {
        float4 a = base[t + (4 * i + 0) * 256];
        float4 bb = base[t + (4 * i + 1) * 256];
        float4 c = base[t + (4 * i + 2) * 256];
        float4 d = base[t + (4 * i + 3) * 256];
        m0 = fmaxf(m0, fmaxf(fmaxf(a.x, a.y), fmaxf(a.z, a.w)));
        m1 = fmaxf(m1, fmaxf(fmaxf(bb.x, bb.y), fmaxf(bb.z, bb.w)));
        m2 = fmaxf(m2, fmaxf(fmaxf(c.x, c.y), fmaxf(c.z, c.w)));
        m3 = fmaxf(m3, fmaxf(fmaxf(d.x, d.y), fmaxf(d.z, d.w)));
    }
    float m = fmaxf(fmaxf(m0, m1), fmaxf(m2, m3));

    #pragma unroll
    for (int off = 16; off > 0; off >>= 1)
        m = fmaxf(m, __shfl_xor_sync(0xFFFFFFFFu, m, off));

    __shared__ float s_red[8];
    __shared__ unsigned s_ticket;
    if ((t & 31) == 0) s_red[t >> 5] = m;
    __syncthreads();
    if (t == 0) {
        float r = s_red[0];
        #pragma unroll
        for (int w = 1; w < 8; w++) r = fmaxf(r, s_red[w]);
        d_gp[bc] = r;
        __threadfence();                       // release (thread 0 ONLY)
        s_ticket = atomicAdd(&d_count[b], 1u); // ticket on this batch
    }
    __syncthreads();
    if (s_ticket != 127u) return;

    // ---- winner block for batch b: compute its 128 gates ----
    if (t == 0) d_count[b] = 0;  // reset for next graph replay (all peers done)

    __shared__ float s_gp[128];
    __shared__ float s_h[128];
    if (t < 128) s_gp[t] = d_gp[b * 128 + t];  // cold L1 -> L2 (up to date)
    __syncthreads();

    if (t < 128) {
        const float* w1row = w1 + t * 128;
        float a0 = 0.f, a1 = 0.f, a2 = 0.f, a3 = 0.f;
        #pragma unroll 8
        for (int j = 0; j < 128; j += 4) {
            a0 = fmaf(s_gp[j + 0], w1row[j + 0], a0);
            a1 = fmaf(s_gp[j + 1], w1row[j + 1], a1);
            a2 = fmaf(s_gp[j + 2], w1row[j + 2], a2);
            a3 = fmaf(s_gp[j + 3], w1row[j + 3], a3);
        }
        s_h[t] = fmaxf((a0 + a1) + (a2 + a3) + b1[t], 0.0f);
    }
    __syncthreads();

    if (t < 128) {
        const float* w2row = w2 + t * 128;
        float a0 = 0.f, a1 = 0.f, a2 = 0.f, a3 = 0.f;
        #pragma unroll 8
        for (int j = 0; j < 128; j += 4) {
            a0 = fmaf(s_h[j + 0], w2row[j + 0], a0);
            a1 = fmaf(s_h[j + 1], w2row[j + 1], a1);
            a2 = fmaf(s_h[j + 2], w2row[j + 2], a2);
            a3 = fmaf(s_h[j + 3], w2row[j + 3], a3);
        }
        float z = (a0 + a1) + (a2 + a3) + b2[t];
        d_gate[b * 128 + t] = 1.0f / (1.0f + __expf(-z));
    }
}

// ------- Kernel 2: broadcast scale -------
// 2 blocks per (b,c) slice (grid=2048) for better balance/occupancy.
// 256 threads x 32 float4 each. Streaming stores; default-policy loads.
__global__ __launch_bounds__(256) void scale_kernel(const float4* __restrict__ x4,
                                                    float4* __restrict__ o4) {
    const int blk = (2 * BC - 1) - blockIdx.x;  // reverse order (free; L2 tail)
    const int bc = blk >> 1;
    const int half = blk & 1;
    const float g = d_gate[bc];
    const size_t off = (size_t)bc * SLICE4 + (size_t)half * (SLICE4 / 2);
    const float4* src = x4 + off;
    float4* dst = o4 + off;
    const int t = threadIdx.x;

    #pragma unroll
    for (int i = 0; i < 32; i++) {
        float4 v = src[t + i * 256];
        v.x *= g; v.y *= g; v.z *= g; v.w *= g;
        __stcs(dst + t + i * 256, v);
    }
}

extern "C" void kernel_launch(void* const* d_in, const int* in_sizes, int n_in,
                              void* d_out, int out_size) {
    const float* x  = (const float*)d_in[0];
    const float* w1 = (const float*)d_in[1];
    const float* b1 = (const float*)d_in[2];
    const float* w2 = (const float*)d_in[3];
    const float* b2 = (const float*)d_in[4];
    float* out = (float*)d_out;

    reduce_mlp_kernel<<<BC, 256>>>((const float4*)x, w1, b1, w2, b2);
    scale_kernel<<<2 * BC, 256>>>((const float4*)x, (float4*)out);
}

// round 12
// speedup vs baseline: 1.2843x; 1.2843x over previous
#include <cuda_runtime.h>
#include <math.h>

// Shapes (fixed):
//   x  : [B=8, C=128, D=4, H=128, W=128] -> 67,108,864 fp32 (256 MB)
//   w1, w2 : [C, C] row-major (w[o,c] = w[o*128 + c]); b1, b2 : [C]
// out = x * sigmoid(W2 @ relu(W1 @ max_{dhw}(x) + b1) + b2), gate per (b,c).

#define BC 1024              // B*C slices
#define SLICE4 16384         // 65536 floats / 4 per (b,c)

__device__ float d_gp[BC];   // per-(b,c) global max

// ---------------- Kernel 1: per-slice max reduce (proven 42.8us) ----------------
__global__ __launch_bounds__(256) void max_reduce_kernel(const float4* __restrict__ x4) {
    const int bc = blockIdx.x;
    const float4* base = x4 + (size_t)bc * SLICE4;
    const int t = threadIdx.x;

    float m0 = -INFINITY, m1 = -INFINITY, m2 = -INFINITY, m3 = -INFINITY;
    #pragma unroll
    for (int i = 0; i < 16; i++) {
        float4 a = base[t + (4 * i + 0) * 256];
        float4 b = base[t + (4 * i + 1) * 256];
        float4 c = base[t + (4 * i + 2) * 256];
        float4 d = base[t + (4 * i + 3) * 256];
        m0 = fmaxf(m0, fmaxf(fmaxf(a.x, a.y), fmaxf(a.z, a.w)));
        m1 = fmaxf(m1, fmaxf(fmaxf(b.x, b.y), fmaxf(b.z, b.w)));
        m2 = fmaxf(m2, fmaxf(fmaxf(c.x, c.y), fmaxf(c.z, c.w)));
        m3 = fmaxf(m3, fmaxf(fmaxf(d.x, d.y), fmaxf(d.z, d.w)));
    }
    float m = fmaxf(fmaxf(m0, m1), fmaxf(m2, m3));

    #pragma unroll
    for (int off = 16; off > 0; off >>= 1)
        m = fmaxf(m, __shfl_xor_sync(0xFFFFFFFFu, m, off));

    __shared__ float s[8];
    if ((t & 31) == 0) s[t >> 5] = m;
    __syncthreads();
    if (t == 0) {
        float r = s[0];
        #pragma unroll
        for (int w = 1; w < 8; w++) r = fmaxf(r, s[w]);
        d_gp[bc] = r;
    }
}

// -------- Kernel 2: scale with per-block inline gate computation --------
// One block per (b,c) slice. d_gp is complete at kernel start (launch boundary
// = full sync; no fences). Each block computes its OWN single gate value:
//   h = relu(W1 @ gp[b] + b1)          (full 128-vector, warp-per-channel)
//   g = sigmoid(dot(h, w2[co,:]) + b2[co])
// W1/W2 live in L2 after the first blocks touch them (64KB each).
// ALU is idle in this DRAM-bound kernel (issue=4%), so the gate is ~free.
__global__ __launch_bounds__(256) void scale_gate_kernel(const float4* __restrict__ x4,
                                                         float4* __restrict__ o4,
                                                         const float* __restrict__ w1,
                                                         const float* __restrict__ b1,
                                                         const float* __restrict__ w2,
                                                         const float* __restrict__ b2) {
    const int bc = blockIdx.x;
    const int b = bc >> 7;        // batch
    const int co = bc & 127;      // this block's output channel
    const int t = threadIdx.x;
    const int wid = t >> 5, lane = t & 31;

    __shared__ float s_gp[128];
    __shared__ float s_h[128];
    __shared__ float s_part[8];
    __shared__ float s_gate;

    if (t < 128) s_gp[t] = d_gp[b * 128 + t];
    __syncthreads();

    // ---- layer 1: warp w computes output channels [w*16, w*16+16) ----
    // Lanes span the 128-float weight row (float4 each) -> coalesced L2 reads.
    {
        const float4* gp4 = (const float4*)s_gp;
        float4 gv = gp4[lane];    // this lane's 4 gp values (fixed across channels)
        #pragma unroll
        for (int k = 0; k < 16; k++) {
            int c = wid * 16 + k;
            float4 wv = ((const float4*)(w1 + c * 128))[lane];
            float p = fmaf(gv.x, wv.x, fmaf(gv.y, wv.y, fmaf(gv.z, wv.z, gv.w * wv.w)));
            #pragma unroll
            for (int off = 16; off > 0; off >>= 1)
                p += __shfl_xor_sync(0xFFFFFFFFu, p, off);
            if (lane == 0) s_h[c] = fmaxf(p + b1[c], 0.0f);
        }
    }
    __syncthreads();

    // ---- layer 2: single dot  gate = sigmoid(<h, w2[co,:]> + b2[co]) ----
    {
        float p = (t < 128) ? s_h[t] * w2[co * 128 + t] : 0.0f;
        #pragma unroll
        for (int off = 16; off > 0; off >>= 1)
            p += __shfl_xor_sync(0xFFFFFFFFu, p, off);
        if (lane == 0) s_part[wid] = p;
        __syncthreads();
        if (t == 0) {
            float z = b2[co];
            #pragma unroll
            for (int w = 0; w < 8; w++) z += s_part[w];
            s_gate = 1.0f / (1.0f + __expf(-z));
        }
    }
    __syncthreads();
    const float g = s_gate;

    // ---- stream: 256 threads x 64 float4, coalesced; evict-first stores ----
    const float4* src = x4 + (size_t)bc * SLICE4;
    float4* dst = o4 + (size_t)bc * SLICE4;
    #pragma unroll
    for (int i = 0; i < 64; i++) {
        float4 v = src[t + i * 256];
        v.x *= g; v.y *= g; v.z *= g; v.w *= g;
        __stcs(dst + t + i * 256, v);
    }
}

extern "C" void kernel_launch(void* const* d_in, const int* in_sizes, int n_in,
                              void* d_out, int out_size) {
    const float* x  = (const float*)d_in[0];
    const float* w1 = (const float*)d_in[1];
    const float* b1 = (const float*)d_in[2];
    const float* w2 = (const float*)d_in[3];
    const float* b2 = (const float*)d_in[4];
    float* out = (float*)d_out;

    max_reduce_kernel<<<BC, 256>>>((const float4*)x);
    scale_gate_kernel<<<BC, 256>>>((const float4*)x, (float4*)out, w1, b1, w2, b2);
}